// round 2
// baseline (speedup 1.0000x reference)
#include <cuda_runtime.h>

// Problem constants
#define NB 4
#define NT 4096
#define NC 1024
#define NH 64
#define SSTR 68   // attn smem row stride (floats); 272B, 16B-aligned

// Scratch for projected q, k, v: [B, T, H] fp32 each (4 MB each)
__device__ float g_k[NB * NT * NH];
__device__ float g_q[NB * NT * NH];
__device__ float g_v[NB * NT * NH];

// ---- packed fp32x2 helpers (sm_103a FFMA2 — PTX-only path) ----------------
__device__ __forceinline__ void fma2(unsigned long long& d,
                                     unsigned long long a,
                                     unsigned long long b) {
    asm("fma.rn.f32x2 %0, %1, %2, %0;" : "+l"(d) : "l"(a), "l"(b));
}
__device__ __forceinline__ unsigned long long pack2(float lo, float hi) {
    unsigned long long r;
    asm("mov.b64 %0, {%1, %2};" : "=l"(r) : "f"(lo), "f"(hi));
    return r;
}
__device__ __forceinline__ float2 unpack2(unsigned long long v) {
    float2 f;
    asm("mov.b64 {%0, %1}, %2;" : "=f"(f.x), "=f"(f.y) : "l"(v));
    return f;
}

// ---------------------------------------------------------------------------
// Kernel 1: projections. out[b,t,h] = sum_c x[b,t,c] * W[h,c]
// Tile: 256 rows x 64 cols, BK=16, 256 threads, 8x8 micro-tile, FFMA2 math.
// grid = (64, 3): y selects {Wk, Wq, Wv}. Q scaled by C^-0.5 = 1/32.
// ---------------------------------------------------------------------------
#define PM 256
#define ASTR (PM + 4)   // 260: As store banks = tid -> conflict-free
#define BSTR 68

__global__ __launch_bounds__(256) void proj_kernel(
    const float* __restrict__ x,
    const float* __restrict__ Wk,
    const float* __restrict__ Wq,
    const float* __restrict__ Wv)
{
    __shared__ float As[16][ASTR];   // As[k][m] (k-major)
    __shared__ float Bs[16][BSTR];   // Bs[k][h]

    const float* W;
    float* out;
    float scale = 1.0f;
    if (blockIdx.y == 0)      { W = Wk; out = g_k; }
    else if (blockIdx.y == 1) { W = Wq; out = g_q; scale = 0.03125f; }
    else                      { W = Wv; out = g_v; }

    const int m0  = blockIdx.x * PM;
    const int tid = threadIdx.x;
    const int ty  = tid >> 3;       // 0..31 -> output rows 8*ty .. +7
    const int tx  = tid & 7;        // 0..7  -> output cols 8*tx .. +7
    const int wr  = tid & 63;       // W row loaded by this thread
    const int wu  = tid >> 6;       // W col-group {0..3} -> cols 4*wu..+3

    unsigned long long acc[8][4];
    #pragma unroll
    for (int i = 0; i < 8; i++)
        #pragma unroll
        for (int j = 0; j < 4; j++) acc[i][j] = 0ull;   // (0.f, 0.f)

    for (int k0 = 0; k0 < NC; k0 += 16) {
        float4 xv[4];
        #pragma unroll
        for (int u = 0; u < 4; u++)
            xv[u] = *(const float4*)&x[(m0 + tid) * NC + k0 + 4 * u];
        float4 wv = *(const float4*)&W[wr * NC + k0 + 4 * wu];

        __syncthreads();
        #pragma unroll
        for (int u = 0; u < 4; u++) {          // transpose x into As[k][m]
            As[4 * u + 0][tid] = xv[u].x;
            As[4 * u + 1][tid] = xv[u].y;
            As[4 * u + 2][tid] = xv[u].z;
            As[4 * u + 3][tid] = xv[u].w;
        }
        Bs[4 * wu + 0][wr] = wv.x;
        Bs[4 * wu + 1][wr] = wv.y;
        Bs[4 * wu + 2][wr] = wv.z;
        Bs[4 * wu + 3][wr] = wv.w;
        __syncthreads();

        #pragma unroll
        for (int kk = 0; kk < 16; kk++) {
            float4 a0 = *(const float4*)&As[kk][8 * ty];
            float4 a1 = *(const float4*)&As[kk][8 * ty + 4];
            float4 b0 = *(const float4*)&Bs[kk][8 * tx];
            float4 b1 = *(const float4*)&Bs[kk][8 * tx + 4];

            unsigned long long bb[4];
            bb[0] = pack2(b0.x, b0.y); bb[1] = pack2(b0.z, b0.w);
            bb[2] = pack2(b1.x, b1.y); bb[3] = pack2(b1.z, b1.w);

            unsigned long long aa[8];
            aa[0] = pack2(a0.x, a0.x); aa[1] = pack2(a0.y, a0.y);
            aa[2] = pack2(a0.z, a0.z); aa[3] = pack2(a0.w, a0.w);
            aa[4] = pack2(a1.x, a1.x); aa[5] = pack2(a1.y, a1.y);
            aa[6] = pack2(a1.z, a1.z); aa[7] = pack2(a1.w, a1.w);

            #pragma unroll
            for (int i = 0; i < 8; i++)
                #pragma unroll
                for (int j = 0; j < 4; j++)
                    fma2(acc[i][j], aa[i], bb[j]);
        }
    }

    #pragma unroll
    for (int i = 0; i < 8; i++) {
        float2 c0 = unpack2(acc[i][0]);
        float2 c1 = unpack2(acc[i][1]);
        float2 c2 = unpack2(acc[i][2]);
        float2 c3 = unpack2(acc[i][3]);
        const int row = m0 + 8 * ty + i;
        *(float4*)&out[row * NH + 8 * tx] =
            make_float4(c0.x * scale, c0.y * scale, c1.x * scale, c1.y * scale);
        *(float4*)&out[row * NH + 8 * tx + 4] =
            make_float4(c2.x * scale, c2.y * scale, c3.x * scale, c3.y * scale);
    }
}

// ---------------------------------------------------------------------------
// Kernel 2: causal flash attention, fp32.
// Br = Bc = 64, d = 64, 256 threads, 4x4 micro-tile, online softmax.
// K is stored d-major (transposed) in smem: Kt[d][col] -> the S-phase K loads
// are contiguous 256B warp sweeps (conflict-free) instead of 8-way conflicted.
// ---------------------------------------------------------------------------
__global__ __launch_bounds__(256) void attn_kernel(float* __restrict__ out)
{
    extern __shared__ float sm[];
    float* Qs = sm;                   // [64][SSTR] row-major (q rows)
    float* Kt = Qs + 64 * SSTR;       // [64][SSTR] d-major: Kt[d][kv_col]
    float* Vs = Kt + 64 * SSTR;       // [64][SSTR] row-major (kv rows)
    float* Ps = Vs + 64 * SSTR;       // [64][SSTR]

    const int bx = blockIdx.x;
    const int qt = 63 - (bx >> 2);    // query tile, longest work first
    const int b  = bx & 3;            // batch

    const int tid  = threadIdx.x;
    const int ty   = tid >> 4;
    const int tx   = tid & 15;
    const int lr   = tid >> 2;        // load row 0..63
    const int lc16 = (tid & 3) * 16;  // load col group: 16 floats

    const float* qg = g_q + (b * NT + qt * 64) * NH;
    const float* kg = g_k + b * NT * NH;
    const float* vg = g_v + b * NT * NH;

    #pragma unroll
    for (int u = 0; u < 4; u++) {
        *(float4*)&Qs[lr * SSTR + lc16 + 4 * u] =
            *(const float4*)&qg[lr * NH + lc16 + 4 * u];
    }

    float o[4][4] = {};
    float m[4] = { -INFINITY, -INFINITY, -INFINITY, -INFINITY };
    float l[4] = {};

    const int row0 = qt * 64 + ty * 4;

    for (int j = 0; j <= qt; j++) {
        __syncthreads();   // prior tile's smem reads complete
        const float* kb = kg + j * 64 * NH;
        const float* vb = vg + j * 64 * NH;
        #pragma unroll
        for (int u = 0; u < 4; u++) {
            const int c = lc16 + 4 * u;
            float4 kv4 = *(const float4*)&kb[lr * NH + c];
            Kt[(c + 0) * SSTR + lr] = kv4.x;     // transpose K: Kt[d][col]
            Kt[(c + 1) * SSTR + lr] = kv4.y;
            Kt[(c + 2) * SSTR + lr] = kv4.z;
            Kt[(c + 3) * SSTR + lr] = kv4.w;
            *(float4*)&Vs[lr * SSTR + c] = *(const float4*)&vb[lr * NH + c];
        }
        __syncthreads();

        // ---- S = Q K^T: q rows from Qs (broadcast), K from Kt (conflict-free)
        float s[4][4] = {};
        #pragma unroll 4
        for (int d = 0; d < 64; d += 4) {
            float4 q0 = *(const float4*)&Qs[(ty * 4 + 0) * SSTR + d];
            float4 q1 = *(const float4*)&Qs[(ty * 4 + 1) * SSTR + d];
            float4 q2 = *(const float4*)&Qs[(ty * 4 + 2) * SSTR + d];
            float4 q3 = *(const float4*)&Qs[(ty * 4 + 3) * SSTR + d];
            float4 k0 = *(const float4*)&Kt[(d + 0) * SSTR + tx * 4];
            float4 k1 = *(const float4*)&Kt[(d + 1) * SSTR + tx * 4];
            float4 k2 = *(const float4*)&Kt[(d + 2) * SSTR + tx * 4];
            float4 k3 = *(const float4*)&Kt[(d + 3) * SSTR + tx * 4];
            // k{r}.j = K[4*tx + j][d + r]
            s[0][0] += q0.x*k0.x + q0.y*k1.x + q0.z*k2.x + q0.w*k3.x;
            s[0][1] += q0.x*k0.y + q0.y*k1.y + q0.z*k2.y + q0.w*k3.y;
            s[0][2] += q0.x*k0.z + q0.y*k1.z + q0.z*k2.z + q0.w*k3.z;
            s[0][3] += q0.x*k0.w + q0.y*k1.w + q0.z*k2.w + q0.w*k3.w;
            s[1][0] += q1.x*k0.x + q1.y*k1.x + q1.z*k2.x + q1.w*k3.x;
            s[1][1] += q1.x*k0.y + q1.y*k1.y + q1.z*k2.y + q1.w*k3.y;
            s[1][2] += q1.x*k0.z + q1.y*k1.z + q1.z*k2.z + q1.w*k3.z;
            s[1][3] += q1.x*k0.w + q1.y*k1.w + q1.z*k2.w + q1.w*k3.w;
            s[2][0] += q2.x*k0.x + q2.y*k1.x + q2.z*k2.x + q2.w*k3.x;
            s[2][1] += q2.x*k0.y + q2.y*k1.y + q2.z*k2.y + q2.w*k3.y;
            s[2][2] += q2.x*k0.z + q2.y*k1.z + q2.z*k2.z + q2.w*k3.z;
            s[2][3] += q2.x*k0.w + q2.y*k1.w + q2.z*k2.w + q2.w*k3.w;
            s[3][0] += q3.x*k0.x + q3.y*k1.x + q3.z*k2.x + q3.w*k3.x;
            s[3][1] += q3.x*k0.y + q3.y*k1.y + q3.z*k2.y + q3.w*k3.y;
            s[3][2] += q3.x*k0.z + q3.y*k1.z + q3.z*k2.z + q3.w*k3.z;
            s[3][3] += q3.x*k0.w + q3.y*k1.w + q3.z*k2.w + q3.w*k3.w;
        }

        // ---- causal mask (diagonal tile only) ----
        if (j == qt) {
            const int col0 = j * 64 + tx * 4;
            #pragma unroll
            for (int i = 0; i < 4; i++)
                #pragma unroll
                for (int jj = 0; jj < 4; jj++)
                    if (col0 + jj > row0 + i) s[i][jj] = -INFINITY;
        }

        // ---- online softmax update (16-lane row groups) ----
        #pragma unroll
        for (int i = 0; i < 4; i++) {
            float tm = fmaxf(fmaxf(s[i][0], s[i][1]), fmaxf(s[i][2], s[i][3]));
            tm = fmaxf(tm, __shfl_xor_sync(0xffffffffu, tm, 1));
            tm = fmaxf(tm, __shfl_xor_sync(0xffffffffu, tm, 2));
            tm = fmaxf(tm, __shfl_xor_sync(0xffffffffu, tm, 4));
            tm = fmaxf(tm, __shfl_xor_sync(0xffffffffu, tm, 8));
            float mn  = fmaxf(m[i], tm);
            float fac = __expf(m[i] - mn);   // first tile: exp(-inf) = 0
            m[i] = mn;
            float ps = 0.0f;
            #pragma unroll
            for (int jj = 0; jj < 4; jj++) {
                s[i][jj] = __expf(s[i][jj] - mn);
                ps += s[i][jj];
            }
            ps += __shfl_xor_sync(0xffffffffu, ps, 1);
            ps += __shfl_xor_sync(0xffffffffu, ps, 2);
            ps += __shfl_xor_sync(0xffffffffu, ps, 4);
            ps += __shfl_xor_sync(0xffffffffu, ps, 8);
            l[i] = l[i] * fac + ps;
            o[i][0] *= fac; o[i][1] *= fac; o[i][2] *= fac; o[i][3] *= fac;
        }

        // ---- stage P in smem ----
        #pragma unroll
        for (int i = 0; i < 4; i++) {
            *(float4*)&Ps[(ty * 4 + i) * SSTR + tx * 4] =
                make_float4(s[i][0], s[i][1], s[i][2], s[i][3]);
        }
        __syncthreads();

        // ---- O += P V ----
        #pragma unroll 8
        for (int k = 0; k < 64; k++) {
            float4 vv = *(const float4*)&Vs[k * SSTR + tx * 4];
            float p0 = Ps[(ty * 4 + 0) * SSTR + k];
            float p1 = Ps[(ty * 4 + 1) * SSTR + k];
            float p2 = Ps[(ty * 4 + 2) * SSTR + k];
            float p3 = Ps[(ty * 4 + 3) * SSTR + k];
            o[0][0] += p0 * vv.x; o[0][1] += p0 * vv.y; o[0][2] += p0 * vv.z; o[0][3] += p0 * vv.w;
            o[1][0] += p1 * vv.x; o[1][1] += p1 * vv.y; o[1][2] += p1 * vv.z; o[1][3] += p1 * vv.w;
            o[2][0] += p2 * vv.x; o[2][1] += p2 * vv.y; o[2][2] += p2 * vv.z; o[2][3] += p2 * vv.w;
            o[3][0] += p3 * vv.x; o[3][1] += p3 * vv.y; o[3][2] += p3 * vv.z; o[3][3] += p3 * vv.w;
        }
    }

    // ---- epilogue: normalize and store ----
    #pragma unroll
    for (int i = 0; i < 4; i++) {
        float inv = 1.0f / l[i];
        float4 ov = make_float4(o[i][0] * inv, o[i][1] * inv,
                                o[i][2] * inv, o[i][3] * inv);
        *(float4*)&out[(b * NT + row0 + i) * NH + tx * 4] = ov;
    }
}

// ---------------------------------------------------------------------------
extern "C" void kernel_launch(void* const* d_in, const int* in_sizes, int n_in,
                              void* d_out, int out_size)
{
    const float* x  = (const float*)d_in[0];
    const float* Wk = (const float*)d_in[1];
    const float* Wq = (const float*)d_in[2];
    const float* Wv = (const float*)d_in[3];
    float* out = (float*)d_out;

    const int smem_bytes = 4 * 64 * SSTR * sizeof(float);   // 69632 B
    cudaFuncSetAttribute(attn_kernel,
                         cudaFuncAttributeMaxDynamicSharedMemorySize, smem_bytes);

    proj_kernel<<<dim3(NB * NT / PM, 3), 256>>>(x, Wk, Wq, Wv);
    attn_kernel<<<256, 256, smem_bytes>>>(out);
}

// round 15
// speedup vs baseline: 1.5039x; 1.5039x over previous
#include <cuda_runtime.h>

#define NB 4
#define NT 4096
#define NC 1024
#define NH 64

typedef unsigned long long ull;

// Scratch: projections [B,T,H] fp32, plus split-KV partials (2 halves)
__device__ float g_k[NB * NT * NH];
__device__ float g_q[NB * NT * NH];
__device__ float g_v[NB * NT * NH];
__device__ float g_po0[NB * NT * NH];     // unnormalized O, half 0
__device__ float g_po1[NB * NT * NH];     // unnormalized O, half 1
__device__ float g_ml0[NB * NT * 2];      // (m, l) per row, half 0
__device__ float g_ml1[NB * NT * 2];      // (m, l) per row, half 1

// ---- packed fp32x2 helpers (sm_103a FFMA2 — PTX-only path) ----------------
__device__ __forceinline__ void fma2(ull& d, ull a, ull b) {
    asm("fma.rn.f32x2 %0, %1, %2, %0;" : "+l"(d) : "l"(a), "l"(b));
}
__device__ __forceinline__ void mul2(ull& d, ull a) {
    asm("mul.rn.f32x2 %0, %0, %1;" : "+l"(d) : "l"(a));
}
__device__ __forceinline__ ull pack2(float lo, float hi) {
    ull r; asm("mov.b64 %0, {%1, %2};" : "=l"(r) : "f"(lo), "f"(hi)); return r;
}

// zero-cost register-pair aliasing between float4 and 2x f32x2
union F4U {
    float4 f;
    ull    u[2];
    float  s[4];
};

// ---------------------------------------------------------------------------
// Kernel 1: projections. out[b,t,h] = sum_c x[b,t,c] * W[h,c]
// PM=128 rows x 64 cols per CTA, BK=16, 256 threads, 8x4 micro-tile
// (4 packed row-pairs x 4 cols), FFMA2 math, register-prefetched loads.
// As stores XOR-swizzled (col ^ 16 when k>=8) -> conflict-free transpose.
// ---------------------------------------------------------------------------
#define PM 128
#define ASTR 136
#define BSTR 68

__global__ __launch_bounds__(256) void proj_kernel(
    const float* __restrict__ x,
    const float* __restrict__ Wk,
    const float* __restrict__ Wq,
    const float* __restrict__ Wv)
{
    __shared__ float As[16][ASTR];   // As[k][m], m-col swizzled by k bit 3
    __shared__ float Bs[16][BSTR];   // Bs[k][h]

    const float* W;
    float* out;
    float scale = 1.0f;
    if (blockIdx.y == 0)      { W = Wk; out = g_k; }
    else if (blockIdx.y == 1) { W = Wq; out = g_q; scale = 0.03125f; }  // C^-0.5
    else                      { W = Wv; out = g_v; }

    const int m0  = blockIdx.x * PM;
    const int tid = threadIdx.x;
    const int ty  = tid >> 4;        // 0..15 -> rows 8*ty .. +7
    const int tx  = tid & 15;        // 0..15 -> cols 4*tx .. +3
    const int lr2 = tid >> 1;        // 0..127 x-row loaded
    const int lc2 = (tid & 1) * 8;   // x-col group {0,8}
    const int sw2 = (lc2 & 8) << 1;  // As store col swizzle: 0 or 16
    const int wr  = tid & 63;        // W row
    const int wu  = tid >> 6;        // W col-group 0..3

    ull acc[4][4];
    #pragma unroll
    for (int i = 0; i < 4; i++)
        #pragma unroll
        for (int j = 0; j < 4; j++) acc[i][j] = 0ull;

    float4 xa = *(const float4*)&x[(m0 + lr2) * NC + lc2];
    float4 xb = *(const float4*)&x[(m0 + lr2) * NC + lc2 + 4];
    float4 wv = *(const float4*)&W[wr * NC + 4 * wu];

    for (int k0 = 0; k0 < NC; k0 += 16) {
        const int sr = lr2 ^ sw2;    // swizzled store column
        __syncthreads();
        As[lc2 + 0][sr] = xa.x; As[lc2 + 1][sr] = xa.y;
        As[lc2 + 2][sr] = xa.z; As[lc2 + 3][sr] = xa.w;
        As[lc2 + 4][sr] = xb.x; As[lc2 + 5][sr] = xb.y;
        As[lc2 + 6][sr] = xb.z; As[lc2 + 7][sr] = xb.w;
        Bs[4 * wu + 0][wr] = wv.x; Bs[4 * wu + 1][wr] = wv.y;
        Bs[4 * wu + 2][wr] = wv.z; Bs[4 * wu + 3][wr] = wv.w;
        __syncthreads();

        if (k0 + 16 < NC) {          // prefetch next k-tile over this compute
            xa = *(const float4*)&x[(m0 + lr2) * NC + k0 + 16 + lc2];
            xb = *(const float4*)&x[(m0 + lr2) * NC + k0 + 16 + lc2 + 4];
            wv = *(const float4*)&W[wr * NC + k0 + 16 + 4 * wu];
        }

        #pragma unroll
        for (int kk = 0; kk < 16; kk++) {
            const int swk = (kk & 8) << 1;          // load-side swizzle
            F4U a0, a1, b4;
            a0.f = *(const float4*)&As[kk][(8 * ty) ^ swk];
            a1.f = *(const float4*)&As[kk][(8 * ty + 4) ^ swk];
            b4.f = *(const float4*)&Bs[kk][4 * tx];
            ull bd0 = pack2(b4.s[0], b4.s[0]);
            ull bd1 = pack2(b4.s[1], b4.s[1]);
            ull bd2 = pack2(b4.s[2], b4.s[2]);
            ull bd3 = pack2(b4.s[3], b4.s[3]);
            fma2(acc[0][0], a0.u[0], bd0); fma2(acc[0][1], a0.u[0], bd1);
            fma2(acc[0][2], a0.u[0], bd2); fma2(acc[0][3], a0.u[0], bd3);
            fma2(acc[1][0], a0.u[1], bd0); fma2(acc[1][1], a0.u[1], bd1);
            fma2(acc[1][2], a0.u[1], bd2); fma2(acc[1][3], a0.u[1], bd3);
            fma2(acc[2][0], a1.u[0], bd0); fma2(acc[2][1], a1.u[0], bd1);
            fma2(acc[2][2], a1.u[0], bd2); fma2(acc[2][3], a1.u[0], bd3);
            fma2(acc[3][0], a1.u[1], bd0); fma2(acc[3][1], a1.u[1], bd1);
            fma2(acc[3][2], a1.u[1], bd2); fma2(acc[3][3], a1.u[1], bd3);
        }
    }

    #pragma unroll
    for (int r2 = 0; r2 < 4; r2++) {
        F4U c0, c1, c2, c3;
        c0.u[0] = acc[r2][0]; c1.u[0] = acc[r2][1];
        c2.u[0] = acc[r2][2]; c3.u[0] = acc[r2][3];
        const int row = m0 + 8 * ty + 2 * r2;
        *(float4*)&out[row * NH + 4 * tx] =
            make_float4(c0.s[0] * scale, c1.s[0] * scale, c2.s[0] * scale, c3.s[0] * scale);
        *(float4*)&out[(row + 1) * NH + 4 * tx] =
            make_float4(c0.s[1] * scale, c1.s[1] * scale, c2.s[1] * scale, c3.s[1] * scale);
    }
}

// ---------------------------------------------------------------------------
// Kernel 2: causal flash attention, fp32, FFMA2 math, SPLIT-KV (2 halves).
// grid = 512: (qt, b, half). Coalesced loaders (lr = tid>>2). Transposed
// Qt/Kt use XOR column swizzle col' = col ^ (8*((d>>4)&3)): stores hit 32
// distinct banks (conflict-free), loads stay 4-aligned relabelings.
// ---------------------------------------------------------------------------
#define SSTR 68
#define PSTR 132

__global__ __launch_bounds__(256, 2) void attn_kernel()
{
    extern __shared__ float sm[];
    float* Qt = sm;                   // [64 d][SSTR] : Qt[d][q_row ^ sw(d)]
    float* Kt = Qt + 64 * SSTR;       // [64 d][SSTR] : Kt[d][kv_col ^ sw(d)]
    float* Vs = Kt + 64 * SSTR;       // [64 k][SSTR] : row-major
    float* Pd = Vs + 64 * SSTR;       // [64 row][PSTR] : duplicated pairs

    const int bx   = blockIdx.x;
    const int qt   = 63 - (bx >> 3);  // query tile, longest work first
    const int b    = (bx >> 1) & 3;   // batch
    const int half = bx & 1;

    const int n  = qt + 1;
    const int nA = (n + 1) >> 1;
    const int j0 = half ? nA : 0;
    const int j1 = half ? n  : nA;    // half 1 empty when n == 1 (qt == 0)

    const int tid  = threadIdx.x;
    const int ty   = tid >> 4;        // 0..15 -> q rows 4*ty..+3
    const int tx   = tid & 15;        // 0..15 -> kv cols 4*tx..+3
    const int lr   = tid >> 2;        // load row 0..63 (coalesced LDG)
    const int lc16 = (tid & 3) * 16;  // load col group {0,16,32,48}
    const int swc  = (lc16 >> 1) & 24;// store col swizzle (const per thread)
    const int slr  = lr ^ swc;        // swizzled transpose-store column

    const float* qg = g_q + (b * NT + qt * 64) * NH;
    const float* kg = g_k + b * NT * NH;
    const float* vg = g_v + b * NT * NH;

    // Load Q transposed + swizzled: conflict-free stores, coalesced LDG
    #pragma unroll
    for (int u = 0; u < 4; u++) {
        const int c = lc16 + 4 * u;
        float4 q4 = *(const float4*)&qg[lr * NH + c];
        Qt[(c + 0) * SSTR + slr] = q4.x;
        Qt[(c + 1) * SSTR + slr] = q4.y;
        Qt[(c + 2) * SSTR + slr] = q4.z;
        Qt[(c + 3) * SSTR + slr] = q4.w;
    }

    // Prefetch first K/V tile of this half
    float4 kpf[4], vpf[4];
    if (j0 < j1) {
        const float* kb = kg + j0 * 64 * NH;
        const float* vb = vg + j0 * 64 * NH;
        #pragma unroll
        for (int u = 0; u < 4; u++) {
            kpf[u] = *(const float4*)&kb[lr * NH + lc16 + 4 * u];
            vpf[u] = *(const float4*)&vb[lr * NH + lc16 + 4 * u];
        }
    }

    ull o2[4][2];
    #pragma unroll
    for (int i = 0; i < 4; i++) { o2[i][0] = 0ull; o2[i][1] = 0ull; }
    float m[4] = { -INFINITY, -INFINITY, -INFINITY, -INFINITY };
    float l[4] = {};

    const int row0 = qt * 64 + ty * 4;

    for (int j = j0; j < j1; j++) {
        __syncthreads();   // prior step's smem reads complete
        #pragma unroll
        for (int u = 0; u < 4; u++) {
            const int c = lc16 + 4 * u;
            Kt[(c + 0) * SSTR + slr] = kpf[u].x;   // swizzled transpose
            Kt[(c + 1) * SSTR + slr] = kpf[u].y;
            Kt[(c + 2) * SSTR + slr] = kpf[u].z;
            Kt[(c + 3) * SSTR + slr] = kpf[u].w;
            *(float4*)&Vs[lr * SSTR + c] = vpf[u];
        }
        __syncthreads();

        if (j + 1 < j1) {   // prefetch next tile over this compute
            const float* kb = kg + (j + 1) * 64 * NH;
            const float* vb = vg + (j + 1) * 64 * NH;
            #pragma unroll
            for (int u = 0; u < 4; u++) {
                kpf[u] = *(const float4*)&kb[lr * NH + lc16 + 4 * u];
                vpf[u] = *(const float4*)&vb[lr * NH + lc16 + 4 * u];
            }
        }

        // ---- S = Q K^T, rows-packed FFMA2 ----
        ull s2[2][4] = { {0,0,0,0}, {0,0,0,0} };
        #pragma unroll 8
        for (int d = 0; d < 64; d++) {
            const int swd = (d >> 1) & 24;         // load-side swizzle
            F4U q4, k4;
            q4.f = *(const float4*)&Qt[d * SSTR + ((4 * ty) ^ swd)];
            k4.f = *(const float4*)&Kt[d * SSTR + ((4 * tx) ^ swd)];
            ull kd0 = pack2(k4.s[0], k4.s[0]);
            ull kd1 = pack2(k4.s[1], k4.s[1]);
            ull kd2 = pack2(k4.s[2], k4.s[2]);
            ull kd3 = pack2(k4.s[3], k4.s[3]);
            fma2(s2[0][0], q4.u[0], kd0); fma2(s2[0][1], q4.u[0], kd1);
            fma2(s2[0][2], q4.u[0], kd2); fma2(s2[0][3], q4.u[0], kd3);
            fma2(s2[1][0], q4.u[1], kd0); fma2(s2[1][1], q4.u[1], kd1);
            fma2(s2[1][2], q4.u[1], kd2); fma2(s2[1][3], q4.u[1], kd3);
        }

        float s[4][4];
        #pragma unroll
        for (int c = 0; c < 4; c++) {
            F4U u0, u1;
            u0.u[0] = s2[0][c]; u1.u[0] = s2[1][c];
            s[0][c] = u0.s[0]; s[1][c] = u0.s[1];
            s[2][c] = u1.s[0]; s[3][c] = u1.s[1];
        }

        // ---- causal mask (diagonal tile only) ----
        if (j == qt) {
            const int col0 = j * 64 + tx * 4;
            #pragma unroll
            for (int i = 0; i < 4; i++)
                #pragma unroll
                for (int jj = 0; jj < 4; jj++)
                    if (col0 + jj > row0 + i) s[i][jj] = -INFINITY;
        }

        // ---- online softmax (16-lane row groups) ----
        float fac[4];
        #pragma unroll
        for (int i = 0; i < 4; i++) {
            float tm = fmaxf(fmaxf(s[i][0], s[i][1]), fmaxf(s[i][2], s[i][3]));
            tm = fmaxf(tm, __shfl_xor_sync(0xffffffffu, tm, 1));
            tm = fmaxf(tm, __shfl_xor_sync(0xffffffffu, tm, 2));
            tm = fmaxf(tm, __shfl_xor_sync(0xffffffffu, tm, 4));
            tm = fmaxf(tm, __shfl_xor_sync(0xffffffffu, tm, 8));
            float mn = fmaxf(m[i], tm);
            fac[i] = __expf(m[i] - mn);   // first tile: exp(-inf) = 0
            m[i] = mn;
            float ps = 0.0f;
            #pragma unroll
            for (int jj = 0; jj < 4; jj++) {
                s[i][jj] = __expf(s[i][jj] - mn);   // masked: exp(-inf) = 0
                ps += s[i][jj];
            }
            ps += __shfl_xor_sync(0xffffffffu, ps, 1);
            ps += __shfl_xor_sync(0xffffffffu, ps, 2);
            ps += __shfl_xor_sync(0xffffffffu, ps, 4);
            ps += __shfl_xor_sync(0xffffffffu, ps, 8);
            l[i] = l[i] * fac[i] + ps;
        }
        #pragma unroll
        for (int i = 0; i < 4; i++) {
            ull fd = pack2(fac[i], fac[i]);
            mul2(o2[i][0], fd);
            mul2(o2[i][1], fd);
        }

        // ---- stage P duplicated: Pd[row][2k] = (p, p) ----
        #pragma unroll
        for (int i = 0; i < 4; i++) {
            *(float4*)&Pd[(4 * ty + i) * PSTR + 8 * tx] =
                make_float4(s[i][0], s[i][0], s[i][1], s[i][1]);
            *(float4*)&Pd[(4 * ty + i) * PSTR + 8 * tx + 4] =
                make_float4(s[i][2], s[i][2], s[i][3], s[i][3]);
        }
        __syncthreads();

        // ---- O += P V, cols-packed FFMA2, 2 k-steps per iter ----
        #pragma unroll 4
        for (int k = 0; k < 64; k += 2) {
            F4U va, vb;
            va.f = *(const float4*)&Vs[(k + 0) * SSTR + 4 * tx];
            vb.f = *(const float4*)&Vs[(k + 1) * SSTR + 4 * tx];
            F4U p0, p1, p2, p3;   // (p_k dup, p_{k+1} dup) per row
            p0.f = *(const float4*)&Pd[(4 * ty + 0) * PSTR + 2 * k];
            p1.f = *(const float4*)&Pd[(4 * ty + 1) * PSTR + 2 * k];
            p2.f = *(const float4*)&Pd[(4 * ty + 2) * PSTR + 2 * k];
            p3.f = *(const float4*)&Pd[(4 * ty + 3) * PSTR + 2 * k];
            fma2(o2[0][0], p0.u[0], va.u[0]); fma2(o2[0][1], p0.u[0], va.u[1]);
            fma2(o2[1][0], p1.u[0], va.u[0]); fma2(o2[1][1], p1.u[0], va.u[1]);
            fma2(o2[2][0], p2.u[0], va.u[0]); fma2(o2[2][1], p2.u[0], va.u[1]);
            fma2(o2[3][0], p3.u[0], va.u[0]); fma2(o2[3][1], p3.u[0], va.u[1]);
            fma2(o2[0][0], p0.u[1], vb.u[0]); fma2(o2[0][1], p0.u[1], vb.u[1]);
            fma2(o2[1][0], p1.u[1], vb.u[0]); fma2(o2[1][1], p1.u[1], vb.u[1]);
            fma2(o2[2][0], p2.u[1], vb.u[0]); fma2(o2[2][1], p2.u[1], vb.u[1]);
            fma2(o2[3][0], p3.u[1], vb.u[0]); fma2(o2[3][1], p3.u[1], vb.u[1]);
        }
    }

    // ---- epilogue: write UNNORMALIZED partials + (m, l) per row ----
    float* po = half ? g_po1 : g_po0;
    float* ml = half ? g_ml1 : g_ml0;
    #pragma unroll
    for (int i = 0; i < 4; i++) {
        F4U lo, hi;
        lo.u[0] = o2[i][0]; hi.u[0] = o2[i][1];
        const int grow = b * NT + row0 + i;
        *(float4*)&po[grow * NH + 4 * tx] =
            make_float4(lo.s[0], lo.s[1], hi.s[0], hi.s[1]);
        if (tx == 0) {
            ml[grow * 2 + 0] = m[i];
            ml[grow * 2 + 1] = l[i];
        }
    }
}

// ---------------------------------------------------------------------------
// Kernel 3: merge the two split-KV partials. One float4 per thread.
// ---------------------------------------------------------------------------
__global__ __launch_bounds__(256) void reduce_kernel(float* __restrict__ out)
{
    const int idx = blockIdx.x * 256 + threadIdx.x;
    const int row = idx >> 4;
    const int c4  = (idx & 15) * 4;

    float m1 = g_ml0[row * 2], l1 = g_ml0[row * 2 + 1];
    float m2 = g_ml1[row * 2], l2 = g_ml1[row * 2 + 1];
    float M  = fmaxf(m1, m2);
    float w1 = __expf(m1 - M);          // empty half: exp(-inf) = 0
    float w2 = __expf(m2 - M);
    float inv = 1.0f / (l1 * w1 + l2 * w2);

    float4 o1 = *(const float4*)&g_po0[row * NH + c4];
    float4 oB = *(const float4*)&g_po1[row * NH + c4];
    float4 r;
    r.x = (o1.x * w1 + oB.x * w2) * inv;
    r.y = (o1.y * w1 + oB.y * w2) * inv;
    r.z = (o1.z * w1 + oB.z * w2) * inv;
    r.w = (o1.w * w1 + oB.w * w2) * inv;
    *(float4*)&out[row * NH + c4] = r;
}

// ---------------------------------------------------------------------------
extern "C" void kernel_launch(void* const* d_in, const int* in_sizes, int n_in,
                              void* d_out, int out_size)
{
    const float* x  = (const float*)d_in[0];
    const float* Wk = (const float*)d_in[1];
    const float* Wq = (const float*)d_in[2];
    const float* Wv = (const float*)d_in[3];
    float* out = (float*)d_out;

    const int smem_bytes = (3 * 64 * SSTR + 64 * PSTR) * sizeof(float);  // 86016 B
    cudaFuncSetAttribute(attn_kernel,
                         cudaFuncAttributeMaxDynamicSharedMemorySize, smem_bytes);

    proj_kernel<<<dim3(NB * NT / PM, 3), 256>>>(x, Wk, Wq, Wv);
    attn_kernel<<<512, 256, smem_bytes>>>();
    reduce_kernel<<<NB * NT * NH / 4 / 256, 256>>>(out);
}